// round 4
// baseline (speedup 1.0000x reference)
#include <cuda_runtime.h>

// Problem dims
#define T_DIM 4
#define B_DIM 32
#define C_DIM 512
#define N_DIM 196
#define H_DIM 2048
#define J_DIM (B_DIM * N_DIM)          // 6272 = 49 * 128
#define JW    (J_DIM / 32)             // 196 mask words per (t,h)
#define HJ (H_DIM * J_DIM)             // 12,845,056
#define CJ (C_DIM * J_DIM)             //  3,211,264

// Scratch (static device memory)
__device__ float    g_xT[T_DIM * CJ];       // x transposed: (t, c, j)
__device__ float    g_h[T_DIM * HJ];        // hidden pre-act
__device__ float    g_o[T_DIM * CJ];        // output pre-act
__device__ float    g_w2T[H_DIM * C_DIM];   // w2 transposed to [H, C]
__device__ unsigned g_mask[T_DIM * H_DIM * JW];  // spike bitmask 6.4 MB
__device__ double   g_s1[H_DIM];            // BN1 fused-stats accumulators
__device__ double   g_s2[H_DIM];
__device__ float    g_mean1[H_DIM];
__device__ float    g_rstd1[H_DIM];
__device__ float    g_mean2[C_DIM];
__device__ float    g_rstd2[C_DIM];

// ---------------------------------------------------------------------------
// K0: transpose x (t,b,c,n) -> g_xT (t,c,j=b*n), float4 both sides.
// Also zeroes the BN1 stats accumulators (first 2048 threads).
// ---------------------------------------------------------------------------
__global__ void transpose_x(const float* __restrict__ x) {
    int idx = blockIdx.x * blockDim.x + threadIdx.x;   // over T*CJ/4
    if (idx < H_DIM) { g_s1[idx] = 0.0; g_s2[idx] = 0.0; }
    int base = idx << 2;
    int t   = base / CJ;
    int rem = base - t * CJ;
    int c   = rem / J_DIM;
    int j   = rem - c * J_DIM;
    int b   = j / N_DIM;
    int n   = j - b * N_DIM;                            // n%4==0, n+3<196
    float4 v = *(const float4*)&x[((t * B_DIM + b) * C_DIM + c) * N_DIM + n];
    *(float4*)&g_xT[base] = v;
}

// ---------------------------------------------------------------------------
// K0b: transpose w2 [C,H] -> g_w2T [H,C]
// ---------------------------------------------------------------------------
__global__ void transpose_w2(const float* __restrict__ w2) {
    __shared__ float tile[32][33];
    int h0 = blockIdx.x * 32, c0 = blockIdx.y * 32;
    for (int r = threadIdx.y; r < 32; r += 8)
        tile[r][threadIdx.x] = w2[(c0 + r) * H_DIM + h0 + threadIdx.x];
    __syncthreads();
    for (int r = threadIdx.y; r < 32; r += 8)
        g_w2T[(h0 + r) * C_DIM + c0 + threadIdx.x] = tile[threadIdx.x][r];
}

// ---------------------------------------------------------------------------
// K1: SGEMM h = w1 @ xT per t, with fused fp64 BN1-stats partial epilogue.
// 128x128 tile, BK=8, 256 threads, 8x8/thread (4+64 split), double-buffered.
// ---------------------------------------------------------------------------
__global__ __launch_bounds__(256) void sgemm1(
    const float* __restrict__ A, const float* __restrict__ B,
    float* __restrict__ C) {
    __shared__ float As[2][8][128];
    __shared__ float Bs[2][8][128];

    const float* Bt = B + blockIdx.z * CJ;
    float*       Ct = C + blockIdx.z * HJ;

    int tid = threadIdx.x;
    int m0 = blockIdx.x * 128;
    int n0 = blockIdx.y * 128;

    int arow = tid >> 1;
    int acol = (tid & 1) << 2;
    int brow = tid >> 5;
    int bcol = (tid & 31) << 2;

    const float* Ap = A  + (m0 + arow) * 512 + acol;
    const float* Bp = Bt + brow * J_DIM + n0 + bcol;

    int tx = tid & 15;
    int ty = tid >> 4;

    float acc[8][8];
#pragma unroll
    for (int i = 0; i < 8; i++)
#pragma unroll
        for (int j = 0; j < 8; j++) acc[i][j] = 0.0f;

    float4 a4 = *(const float4*)Ap;
    float4 b4 = *(const float4*)Bp;
    As[0][acol + 0][arow] = a4.x;
    As[0][acol + 1][arow] = a4.y;
    As[0][acol + 2][arow] = a4.z;
    As[0][acol + 3][arow] = a4.w;
    *(float4*)&Bs[0][brow][bcol] = b4;
    __syncthreads();

    int buf = 0;
    for (int k0 = 8; k0 <= 512; k0 += 8) {
        bool more = (k0 < 512);
        if (more) {
            Ap += 8;
            Bp += 8 * J_DIM;
            a4 = *(const float4*)Ap;
            b4 = *(const float4*)Bp;
        }
#pragma unroll
        for (int k = 0; k < 8; k++) {
            float4 ra0 = *(const float4*)&As[buf][k][ty << 2];
            float4 ra1 = *(const float4*)&As[buf][k][(ty << 2) + 64];
            float4 rb0 = *(const float4*)&Bs[buf][k][tx << 2];
            float4 rb1 = *(const float4*)&Bs[buf][k][(tx << 2) + 64];
            float ra[8] = {ra0.x, ra0.y, ra0.z, ra0.w, ra1.x, ra1.y, ra1.z, ra1.w};
            float rb[8] = {rb0.x, rb0.y, rb0.z, rb0.w, rb1.x, rb1.y, rb1.z, rb1.w};
#pragma unroll
            for (int i = 0; i < 8; i++)
#pragma unroll
                for (int j = 0; j < 8; j++)
                    acc[i][j] = fmaf(ra[i], rb[j], acc[i][j]);
        }
        if (more) {
            buf ^= 1;
            As[buf][acol + 0][arow] = a4.x;
            As[buf][acol + 1][arow] = a4.y;
            As[buf][acol + 2][arow] = a4.z;
            As[buf][acol + 3][arow] = a4.w;
            *(float4*)&Bs[buf][brow][bcol] = b4;
            __syncthreads();
        }
    }

#pragma unroll
    for (int i = 0; i < 8; i++) {
        int m = m0 + (ty << 2) + ((i < 4) ? i : (60 + i));
        float* cr = Ct + m * J_DIM + n0 + (tx << 2);
        *(float4*)cr        = make_float4(acc[i][0], acc[i][1], acc[i][2], acc[i][3]);
        *(float4*)(cr + 64) = make_float4(acc[i][4], acc[i][5], acc[i][6], acc[i][7]);
    }

    // Fused BN1 stats: fp64 partial sums per channel (m-row).
    // Lanes 0-15 / 16-31 of each warp share the same 8 m-rows.
#pragma unroll
    for (int i = 0; i < 8; i++) {
        double s1 = 0.0, s2 = 0.0;
#pragma unroll
        for (int j = 0; j < 8; j++) {
            double v = (double)acc[i][j];
            s1 += v;
            s2 += v * v;
        }
#pragma unroll
        for (int off = 8; off > 0; off >>= 1) {
            s1 += __shfl_down_sync(0xffffffffu, s1, off, 16);
            s2 += __shfl_down_sync(0xffffffffu, s2, off, 16);
        }
        if ((tid & 15) == 0) {
            int m = m0 + (ty << 2) + ((i < 4) ? i : (60 + i));
            atomicAdd(&g_s1[m], s1);
            atomicAdd(&g_s2[m], s2);
        }
    }
}

// ---------------------------------------------------------------------------
// BN1 finalize: mean/rstd from fused fp64 sums.
// ---------------------------------------------------------------------------
__global__ void bn1_finalize() {
    int ch = blockIdx.x * blockDim.x + threadIdx.x;
    if (ch >= H_DIM) return;
    double n    = (double)T_DIM * (double)J_DIM;
    double mean = g_s1[ch] / n;
    double var  = g_s2[ch] / n - mean * mean;
    g_mean1[ch] = (float)mean;
    g_rstd1[ch] = __frsqrt_rn(__fadd_rn((float)var, 1e-5f));
}

// ---------------------------------------------------------------------------
// BN1 + LIF1 -> spike bitmask. One warp per (h, 32-j block), all 4 t.
// ---------------------------------------------------------------------------
__global__ __launch_bounds__(256) void lif1_mask(
    const float* __restrict__ gamma, const float* __restrict__ beta) {
    int gw   = (blockIdx.x * 256 + threadIdx.x) >> 5;   // global warp id
    int lane = threadIdx.x & 31;
    int h  = gw / JW;
    int jw = gw - h * JW;
    int j  = (jw << 5) + lane;
    float m = g_mean1[h], r = g_rstd1[h];
    float g = gamma[h],   bt = beta[h];
    const float* p = g_h + h * J_DIM + j;
    float v = 0.0f;
#pragma unroll
    for (int t = 0; t < T_DIM; t++) {
        float x = p[t * HJ];
        x = __fadd_rn(__fmul_rn(__fmul_rn(__fsub_rn(x, m), r), g), bt);
        v = __fadd_rn(v, __fmul_rn(__fsub_rn(x, v), 0.5f));
        unsigned mw = __ballot_sync(0xffffffffu, v >= 1.0f);
        if (lane == 0) g_mask[(t * H_DIM + h) * JW + jw] = mw;
        v = (v >= 1.0f) ? 0.0f : v;
    }
}

// ---------------------------------------------------------------------------
// K4: sparse spike GEMM via smem row-streaming.
// CTA = 64 j-columns x one t, 1024 threads (32 warps).
// Warp w owns columns j0+w and j0+32+w.
// Stream w2T rows through a 32KB smem stage (16 rows), register
// double-buffered; warps accumulate only rows whose spike bit is set.
// ---------------------------------------------------------------------------
#define SP_ROWS 16
__global__ __launch_bounds__(1024) void spmm2() {
    __shared__ float    sh[128 * 65];        // rows stage (8192 used) / epilogue buf
    __shared__ unsigned sMk[SP_ROWS][2];

    int tid  = threadIdx.x;
    int lane = tid & 31;
    int w    = tid >> 5;
    int j0   = blockIdx.x * 64;
    int jw0  = blockIdx.x * 2;
    int t    = blockIdx.y;

    int r0 = tid >> 7;          // 0..7
    int c4 = (tid & 127) << 2;  // float offset 0..508

    // prologue: stage 0 into registers
    float4 nA = *(const float4*)&g_w2T[(r0)     * C_DIM + c4];
    float4 nB = *(const float4*)&g_w2T[(r0 + 8) * C_DIM + c4];
    unsigned nM = 0;
    if (tid < 32)
        nM = g_mask[(t * H_DIM + (tid >> 1)) * JW + jw0 + (tid & 1)];

    float4 aA[4], aB[4];
#pragma unroll
    for (int q = 0; q < 4; q++) {
        aA[q] = make_float4(0.f, 0.f, 0.f, 0.f);
        aB[q] = make_float4(0.f, 0.f, 0.f, 0.f);
    }

    for (int s = 0; s < H_DIM / SP_ROWS; s++) {
        __syncthreads();
        *(float4*)&sh[(r0)     * C_DIM + c4] = nA;
        *(float4*)&sh[(r0 + 8) * C_DIM + c4] = nB;
        if (tid < 32) sMk[tid >> 1][tid & 1] = nM;
        __syncthreads();

        if (s + 1 < H_DIM / SP_ROWS) {
            int h0 = (s + 1) * SP_ROWS;
            nA = *(const float4*)&g_w2T[(h0 + r0)     * C_DIM + c4];
            nB = *(const float4*)&g_w2T[(h0 + r0 + 8) * C_DIM + c4];
            if (tid < 32)
                nM = g_mask[(t * H_DIM + h0 + (tid >> 1)) * JW + jw0 + (tid & 1)];
        }

#pragma unroll
        for (int r = 0; r < SP_ROWS; r++) {
            unsigned b0 = (sMk[r][0] >> w) & 1u;
            unsigned b1 = (sMk[r][1] >> w) & 1u;
            if (b0 | b1) {
                const float* rp = &sh[r * C_DIM + (lane << 2)];
                float4 v0 = *(const float4*)(rp);
                float4 v1 = *(const float4*)(rp + 128);
                float4 v2 = *(const float4*)(rp + 256);
                float4 v3 = *(const float4*)(rp + 384);
                if (b0) {
                    aA[0].x += v0.x; aA[0].y += v0.y; aA[0].z += v0.z; aA[0].w += v0.w;
                    aA[1].x += v1.x; aA[1].y += v1.y; aA[1].z += v1.z; aA[1].w += v1.w;
                    aA[2].x += v2.x; aA[2].y += v2.y; aA[2].z += v2.z; aA[2].w += v2.w;
                    aA[3].x += v3.x; aA[3].y += v3.y; aA[3].z += v3.z; aA[3].w += v3.w;
                }
                if (b1) {
                    aB[0].x += v0.x; aB[0].y += v0.y; aB[0].z += v0.z; aB[0].w += v0.w;
                    aB[1].x += v1.x; aB[1].y += v1.y; aB[1].z += v1.z; aB[1].w += v1.w;
                    aB[2].x += v2.x; aB[2].y += v2.y; aB[2].z += v2.z; aB[2].w += v2.w;
                    aB[3].x += v3.x; aB[3].y += v3.y; aB[3].z += v3.z; aB[3].w += v3.w;
                }
            }
        }
    }

    // Epilogue: stage per-q (128 c-rows x 64 j) for coalesced g_o writes.
#pragma unroll
    for (int q = 0; q < 4; q++) {
        __syncthreads();
        float vA[4] = {aA[q].x, aA[q].y, aA[q].z, aA[q].w};
        float vB[4] = {aB[q].x, aB[q].y, aB[q].z, aB[q].w};
#pragma unroll
        for (int i = 0; i < 4; i++) {
            sh[((lane << 2) + i) * 65 + w]      = vA[i];
            sh[((lane << 2) + i) * 65 + 32 + w] = vB[i];
        }
        __syncthreads();
#pragma unroll
        for (int e0 = 0; e0 < 2; e0++) {
            int e  = tid + e0 * 1024;
            int cl = e >> 4;
            int jj = (e & 15) << 2;
            float4 o;
            o.x = sh[cl * 65 + jj + 0];
            o.y = sh[cl * 65 + jj + 1];
            o.z = sh[cl * 65 + jj + 2];
            o.w = sh[cl * 65 + jj + 3];
            *(float4*)&g_o[t * CJ + (q * 128 + cl) * J_DIM + j0 + jj] = o;
        }
    }
}

// ---------------------------------------------------------------------------
// BN stats (layer 2): one CTA per channel, fp64 accumulate, float4 loads.
// ---------------------------------------------------------------------------
__global__ __launch_bounds__(256) void bn_stats(
    const float* __restrict__ X, int tStride,
    float* __restrict__ meanOut, float* __restrict__ rstdOut) {
    int ch = blockIdx.x;
    const float* base = X + ch * J_DIM;
    double s1 = 0.0, s2 = 0.0;
    for (int t = 0; t < T_DIM; t++) {
        const float* p = base + t * tStride;
        for (int j = threadIdx.x * 4; j < J_DIM; j += 256 * 4) {
            float4 v = *(const float4*)&p[j];
            double a = v.x, b = v.y, c = v.z, d = v.w;
            s1 += a + b + c + d;
            s2 += a * a + b * b + c * c + d * d;
        }
    }
    __shared__ double sh1[256];
    __shared__ double sh2[256];
    sh1[threadIdx.x] = s1;
    sh2[threadIdx.x] = s2;
    __syncthreads();
    for (int s = 128; s > 0; s >>= 1) {
        if (threadIdx.x < s) {
            sh1[threadIdx.x] += sh1[threadIdx.x + s];
            sh2[threadIdx.x] += sh2[threadIdx.x + s];
        }
        __syncthreads();
    }
    if (threadIdx.x == 0) {
        double n    = (double)T_DIM * (double)J_DIM;
        double mean = sh1[0] / n;
        double var  = sh2[0] / n - mean * mean;
        meanOut[ch] = (float)mean;
        rstdOut[ch] = __frsqrt_rn(__fadd_rn((float)var, 1e-5f));
    }
}

// ---------------------------------------------------------------------------
// BN2 + LIF2 + transpose to (T,B,C,N), float4.
// ---------------------------------------------------------------------------
__global__ __launch_bounds__(256) void bn_lif2(
    const float* __restrict__ gamma, const float* __restrict__ beta,
    float* __restrict__ out) {
    int idx = blockIdx.x * blockDim.x + threadIdx.x;   // over CJ/4
    int base = idx << 2;
    int c = base / J_DIM;
    int j = base - c * J_DIM;
    int b = j / N_DIM;
    int n = j - b * N_DIM;
    float m = g_mean2[c], r = g_rstd2[c];
    float g = gamma[c],   bt = beta[c];
    float v0 = 0.f, v1 = 0.f, v2 = 0.f, v3 = 0.f;
#pragma unroll
    for (int t = 0; t < T_DIM; t++) {
        float4 x = *(const float4*)&g_o[base + t * CJ];
        float a0 = __fadd_rn(__fmul_rn(__fmul_rn(__fsub_rn(x.x, m), r), g), bt);
        float a1 = __fadd_rn(__fmul_rn(__fmul_rn(__fsub_rn(x.y, m), r), g), bt);
        float a2 = __fadd_rn(__fmul_rn(__fmul_rn(__fsub_rn(x.z, m), r), g), bt);
        float a3 = __fadd_rn(__fmul_rn(__fmul_rn(__fsub_rn(x.w, m), r), g), bt);
        v0 = __fadd_rn(v0, __fmul_rn(__fsub_rn(a0, v0), 0.5f));
        v1 = __fadd_rn(v1, __fmul_rn(__fsub_rn(a1, v1), 0.5f));
        v2 = __fadd_rn(v2, __fmul_rn(__fsub_rn(a2, v2), 0.5f));
        v3 = __fadd_rn(v3, __fmul_rn(__fsub_rn(a3, v3), 0.5f));
        float4 s;
        s.x = (v0 >= 1.0f) ? 1.0f : 0.0f;
        s.y = (v1 >= 1.0f) ? 1.0f : 0.0f;
        s.z = (v2 >= 1.0f) ? 1.0f : 0.0f;
        s.w = (v3 >= 1.0f) ? 1.0f : 0.0f;
        *(float4*)&out[((t * B_DIM + b) * C_DIM + c) * N_DIM + n] = s;
        v0 = (v0 >= 1.0f) ? 0.0f : v0;
        v1 = (v1 >= 1.0f) ? 0.0f : v1;
        v2 = (v2 >= 1.0f) ? 0.0f : v2;
        v3 = (v3 >= 1.0f) ? 0.0f : v3;
    }
}

// ---------------------------------------------------------------------------
// kernel_launch. Inputs: 0:x 1:w1 2:g1 3:b1 4:w2 5:g2 6:b2
// ---------------------------------------------------------------------------
extern "C" void kernel_launch(void* const* d_in, const int* in_sizes, int n_in,
                              void* d_out, int out_size) {
    const float* x  = (const float*)d_in[0];
    const float* w1 = (const float*)d_in[1];
    const float* g1 = (const float*)d_in[2];
    const float* b1 = (const float*)d_in[3];
    const float* w2 = (const float*)d_in[4];
    const float* g2 = (const float*)d_in[5];
    const float* b2 = (const float*)d_in[6];
    float* out = (float*)d_out;

    float *p_xT, *p_h, *p_o, *p_m2, *p_r2;
    cudaGetSymbolAddress((void**)&p_xT, g_xT);
    cudaGetSymbolAddress((void**)&p_h,  g_h);
    cudaGetSymbolAddress((void**)&p_o,  g_o);
    cudaGetSymbolAddress((void**)&p_m2, g_mean2);
    cudaGetSymbolAddress((void**)&p_r2, g_rstd2);

    transpose_x<<<(T_DIM * CJ / 4) / 256, 256>>>(x);
    transpose_w2<<<dim3(H_DIM / 32, C_DIM / 32), dim3(32, 8)>>>(w2);

    sgemm1<<<dim3(H_DIM / 128, J_DIM / 128, T_DIM), 256>>>(w1, p_xT, p_h);
    bn1_finalize<<<H_DIM / 256, 256>>>();
    lif1_mask<<<(H_DIM * JW) / 8, 256>>>(g1, b1);

    spmm2<<<dim3(J_DIM / 64, T_DIM), 1024>>>();

    bn_stats<<<C_DIM, 256>>>(p_o, CJ, p_m2, p_r2);
    bn_lif2<<<(CJ / 4) / 256, 256>>>(g2, b2, out);
}

// round 5
// speedup vs baseline: 1.2934x; 1.2934x over previous
#include <cuda_runtime.h>

// Problem dims
#define T_DIM 4
#define B_DIM 32
#define C_DIM 512
#define N_DIM 196
#define H_DIM 2048
#define J_DIM (B_DIM * N_DIM)          // 6272 = 49 * 128
#define JW    (J_DIM / 32)             // 196 mask words per (t,h)
#define HJ (H_DIM * J_DIM)             // 12,845,056
#define CJ (C_DIM * J_DIM)             //  3,211,264

// Scratch (static device memory)
__device__ float    g_xT[T_DIM * CJ];       // x transposed: (t, c, j)
__device__ float    g_h[T_DIM * HJ];        // hidden pre-act
__device__ float    g_o[T_DIM * CJ];        // output pre-act
__device__ float    g_w2T[H_DIM * C_DIM];   // w2 transposed to [H, C]
__device__ unsigned g_mask[T_DIM * JW * H_DIM]; // spike bits, layout [t][jw][h]
__device__ float    g_mean1[H_DIM];
__device__ float    g_rstd1[H_DIM];
__device__ float    g_mean2[C_DIM];
__device__ float    g_rstd2[C_DIM];

// ---------------------------------------------------------------------------
// K0: transpose x (t,b,c,n) -> g_xT (t,c,j=b*n), float4 both sides.
// ---------------------------------------------------------------------------
__global__ void transpose_x(const float* __restrict__ x) {
    int idx = blockIdx.x * blockDim.x + threadIdx.x;   // over T*CJ/4
    int base = idx << 2;
    int t   = base / CJ;
    int rem = base - t * CJ;
    int c   = rem / J_DIM;
    int j   = rem - c * J_DIM;
    int b   = j / N_DIM;
    int n   = j - b * N_DIM;                            // n%4==0, n+3<196
    float4 v = *(const float4*)&x[((t * B_DIM + b) * C_DIM + c) * N_DIM + n];
    *(float4*)&g_xT[base] = v;
}

// ---------------------------------------------------------------------------
// K0b: transpose w2 [C,H] -> g_w2T [H,C]
// ---------------------------------------------------------------------------
__global__ void transpose_w2(const float* __restrict__ w2) {
    __shared__ float tile[32][33];
    int h0 = blockIdx.x * 32, c0 = blockIdx.y * 32;
    for (int r = threadIdx.y; r < 32; r += 8)
        tile[r][threadIdx.x] = w2[(c0 + r) * H_DIM + h0 + threadIdx.x];
    __syncthreads();
    for (int r = threadIdx.y; r < 32; r += 8)
        g_w2T[(h0 + r) * C_DIM + c0 + threadIdx.x] = tile[threadIdx.x][r];
}

// ---------------------------------------------------------------------------
// K1: SGEMM h = w1 @ xT per t (exact R2 kernel — proven).
// 128x128 tile, BK=8, 256 threads, 8x8/thread (4+64 split), double-buffered.
// ---------------------------------------------------------------------------
__global__ __launch_bounds__(256) void sgemm1(
    const float* __restrict__ A, const float* __restrict__ B,
    float* __restrict__ C) {
    __shared__ float As[2][8][128];
    __shared__ float Bs[2][8][128];

    const float* Bt = B + blockIdx.z * CJ;
    float*       Ct = C + blockIdx.z * HJ;

    int tid = threadIdx.x;
    int m0 = blockIdx.x * 128;
    int n0 = blockIdx.y * 128;

    int arow = tid >> 1;
    int acol = (tid & 1) << 2;
    int brow = tid >> 5;
    int bcol = (tid & 31) << 2;

    const float* Ap = A  + (m0 + arow) * 512 + acol;
    const float* Bp = Bt + brow * J_DIM + n0 + bcol;

    int tx = tid & 15;
    int ty = tid >> 4;

    float acc[8][8];
#pragma unroll
    for (int i = 0; i < 8; i++)
#pragma unroll
        for (int j = 0; j < 8; j++) acc[i][j] = 0.0f;

    float4 a4 = *(const float4*)Ap;
    float4 b4 = *(const float4*)Bp;
    As[0][acol + 0][arow] = a4.x;
    As[0][acol + 1][arow] = a4.y;
    As[0][acol + 2][arow] = a4.z;
    As[0][acol + 3][arow] = a4.w;
    *(float4*)&Bs[0][brow][bcol] = b4;
    __syncthreads();

    int buf = 0;
    for (int k0 = 8; k0 <= 512; k0 += 8) {
        bool more = (k0 < 512);
        if (more) {
            Ap += 8;
            Bp += 8 * J_DIM;
            a4 = *(const float4*)Ap;
            b4 = *(const float4*)Bp;
        }
#pragma unroll
        for (int k = 0; k < 8; k++) {
            float4 ra0 = *(const float4*)&As[buf][k][ty << 2];
            float4 ra1 = *(const float4*)&As[buf][k][(ty << 2) + 64];
            float4 rb0 = *(const float4*)&Bs[buf][k][tx << 2];
            float4 rb1 = *(const float4*)&Bs[buf][k][(tx << 2) + 64];
            float ra[8] = {ra0.x, ra0.y, ra0.z, ra0.w, ra1.x, ra1.y, ra1.z, ra1.w};
            float rb[8] = {rb0.x, rb0.y, rb0.z, rb0.w, rb1.x, rb1.y, rb1.z, rb1.w};
#pragma unroll
            for (int i = 0; i < 8; i++)
#pragma unroll
                for (int j = 0; j < 8; j++)
                    acc[i][j] = fmaf(ra[i], rb[j], acc[i][j]);
        }
        if (more) {
            buf ^= 1;
            As[buf][acol + 0][arow] = a4.x;
            As[buf][acol + 1][arow] = a4.y;
            As[buf][acol + 2][arow] = a4.z;
            As[buf][acol + 3][arow] = a4.w;
            *(float4*)&Bs[buf][brow][bcol] = b4;
            __syncthreads();
        }
    }

#pragma unroll
    for (int i = 0; i < 8; i++) {
        int m = m0 + (ty << 2) + ((i < 4) ? i : (60 + i));
        float* cr = Ct + m * J_DIM + n0 + (tx << 2);
        *(float4*)cr        = make_float4(acc[i][0], acc[i][1], acc[i][2], acc[i][3]);
        *(float4*)(cr + 64) = make_float4(acc[i][4], acc[i][5], acc[i][6], acc[i][7]);
    }
}

// ---------------------------------------------------------------------------
// BN stats: one CTA per channel, fp64 accumulate, float4 loads (exact R2).
// ---------------------------------------------------------------------------
__global__ __launch_bounds__(256) void bn_stats(
    const float* __restrict__ X, int tStride,
    float* __restrict__ meanOut, float* __restrict__ rstdOut) {
    int ch = blockIdx.x;
    const float* base = X + ch * J_DIM;
    double s1 = 0.0, s2 = 0.0;
    for (int t = 0; t < T_DIM; t++) {
        const float* p = base + t * tStride;
        for (int j = threadIdx.x * 4; j < J_DIM; j += 256 * 4) {
            float4 v = *(const float4*)&p[j];
            double a = v.x, b = v.y, c = v.z, d = v.w;
            s1 += a + b + c + d;
            s2 += a * a + b * b + c * c + d * d;
        }
    }
    __shared__ double sh1[256];
    __shared__ double sh2[256];
    sh1[threadIdx.x] = s1;
    sh2[threadIdx.x] = s2;
    __syncthreads();
    for (int s = 128; s > 0; s >>= 1) {
        if (threadIdx.x < s) {
            sh1[threadIdx.x] += sh1[threadIdx.x + s];
            sh2[threadIdx.x] += sh2[threadIdx.x + s];
        }
        __syncthreads();
    }
    if (threadIdx.x == 0) {
        double n    = (double)T_DIM * (double)J_DIM;
        double mean = sh1[0] / n;
        double var  = sh2[0] / n - mean * mean;
        meanOut[ch] = (float)mean;
        rstdOut[ch] = __frsqrt_rn(__fadd_rn((float)var, 1e-5f));
    }
}

// ---------------------------------------------------------------------------
// BN1 + LIF1 -> spike bitmask only (no 205MB float writes).
// Warp gw: h = gw & 2047, jw = gw >> 11; consecutive warps write
// consecutive mask words in the [t][jw][h] layout.
// ---------------------------------------------------------------------------
__global__ __launch_bounds__(256) void lif1_mask(
    const float* __restrict__ gamma, const float* __restrict__ beta) {
    int gw   = (blockIdx.x << 3) + (threadIdx.x >> 5);  // global warp id
    int lane = threadIdx.x & 31;
    int h  = gw & (H_DIM - 1);
    int jw = gw >> 11;                                   // 0..195
    float m = g_mean1[h], r = g_rstd1[h];
    float g = gamma[h],   bt = beta[h];
    const float* p = g_h + h * J_DIM + (jw << 5) + lane;
    float v = 0.0f;
#pragma unroll
    for (int t = 0; t < T_DIM; t++) {
        float x = p[t * HJ];
        x = __fadd_rn(__fmul_rn(__fmul_rn(__fsub_rn(x, m), r), g), bt);
        v = __fadd_rn(v, __fmul_rn(__fsub_rn(x, v), 0.5f));
        unsigned mw = __ballot_sync(0xffffffffu, v >= 1.0f);
        if (lane == 0) g_mask[(t * JW + jw) * H_DIM + h] = mw;
        v = (v >= 1.0f) ? 0.0f : v;
    }
}

// ---------------------------------------------------------------------------
// K4: sparse spike GEMM (R2-proven phase-2/epilogue; phase 1 is now a
// contiguous 8KB mask load instead of 256KB of float ballots).
// CTA = 32 j-columns x one t; warp w owns column j0+w.
// ---------------------------------------------------------------------------
__global__ __launch_bounds__(1024) void spmm2() {
    __shared__ unsigned words[H_DIM];        // 8 KB
    __shared__ float buf[128 * 33];          // 16.9 KB

    int tid  = threadIdx.x;
    int w    = tid >> 5;                     // warp id = local column
    int lane = tid & 31;
    int j0   = blockIdx.x * 32;
    int t    = blockIdx.y;

    // Phase 1: contiguous mask load for this (t, jw) block.
    {
        const unsigned* mp = g_mask + (t * JW + blockIdx.x) * H_DIM;
        words[tid]        = mp[tid];
        words[tid + 1024] = mp[tid + 1024];
    }
    __syncthreads();

    // Phase 2: accumulate active rows of w2T for column j0+w.
    float4 acc0 = make_float4(0.f, 0.f, 0.f, 0.f);
    float4 acc1 = acc0, acc2 = acc0, acc3 = acc0;
    int c0 = lane << 2;
    for (int wi = 0; wi < H_DIM / 32; wi++) {
        unsigned bit = (words[(wi << 5) + lane] >> w) & 1u;
        unsigned m = __ballot_sync(0xffffffffu, bit);
        while (m) {
            int b = __ffs(m) - 1;
            m &= m - 1;
            int h = (wi << 5) + b;
            const float* rp = g_w2T + h * C_DIM + c0;
            float4 v0 = *(const float4*)(rp);
            float4 v1 = *(const float4*)(rp + 128);
            float4 v2 = *(const float4*)(rp + 256);
            float4 v3 = *(const float4*)(rp + 384);
            acc0.x += v0.x; acc0.y += v0.y; acc0.z += v0.z; acc0.w += v0.w;
            acc1.x += v1.x; acc1.y += v1.y; acc1.z += v1.z; acc1.w += v1.w;
            acc2.x += v2.x; acc2.y += v2.y; acc2.z += v2.z; acc2.w += v2.w;
            acc3.x += v3.x; acc3.y += v3.y; acc3.z += v3.z; acc3.w += v3.w;
        }
    }

    // Epilogue: 4 chunks of 128 c-rows, staged for coalesced writes.
#pragma unroll
    for (int q = 0; q < 4; q++) {
        float4 a = (q == 0) ? acc0 : (q == 1) ? acc1 : (q == 2) ? acc2 : acc3;
        __syncthreads();
        buf[(c0 + 0) * 33 + w] = a.x;
        buf[(c0 + 1) * 33 + w] = a.y;
        buf[(c0 + 2) * 33 + w] = a.z;
        buf[(c0 + 3) * 33 + w] = a.w;
        __syncthreads();
        int c_local = tid >> 3;              // 0..127
        int jj = (tid & 7) << 2;             // 0..28
        float4 o;
        o.x = buf[c_local * 33 + jj + 0];
        o.y = buf[c_local * 33 + jj + 1];
        o.z = buf[c_local * 33 + jj + 2];
        o.w = buf[c_local * 33 + jj + 3];
        *(float4*)&g_o[t * CJ + (q * 128 + c_local) * J_DIM + j0 + jj] = o;
    }
}

// ---------------------------------------------------------------------------
// BN2 + LIF2 + transpose to (T,B,C,N), float4 (exact R2).
// ---------------------------------------------------------------------------
__global__ __launch_bounds__(256) void bn_lif2(
    const float* __restrict__ gamma, const float* __restrict__ beta,
    float* __restrict__ out) {
    int idx = blockIdx.x * blockDim.x + threadIdx.x;   // over CJ/4
    int base = idx << 2;
    int c = base / J_DIM;
    int j = base - c * J_DIM;
    int b = j / N_DIM;
    int n = j - b * N_DIM;
    float m = g_mean2[c], r = g_rstd2[c];
    float g = gamma[c],   bt = beta[c];
    float v0 = 0.f, v1 = 0.f, v2 = 0.f, v3 = 0.f;
#pragma unroll
    for (int t = 0; t < T_DIM; t++) {
        float4 x = *(const float4*)&g_o[base + t * CJ];
        float a0 = __fadd_rn(__fmul_rn(__fmul_rn(__fsub_rn(x.x, m), r), g), bt);
        float a1 = __fadd_rn(__fmul_rn(__fmul_rn(__fsub_rn(x.y, m), r), g), bt);
        float a2 = __fadd_rn(__fmul_rn(__fmul_rn(__fsub_rn(x.z, m), r), g), bt);
        float a3 = __fadd_rn(__fmul_rn(__fmul_rn(__fsub_rn(x.w, m), r), g), bt);
        v0 = __fadd_rn(v0, __fmul_rn(__fsub_rn(a0, v0), 0.5f));
        v1 = __fadd_rn(v1, __fmul_rn(__fsub_rn(a1, v1), 0.5f));
        v2 = __fadd_rn(v2, __fmul_rn(__fsub_rn(a2, v2), 0.5f));
        v3 = __fadd_rn(v3, __fmul_rn(__fsub_rn(a3, v3), 0.5f));
        float4 s;
        s.x = (v0 >= 1.0f) ? 1.0f : 0.0f;
        s.y = (v1 >= 1.0f) ? 1.0f : 0.0f;
        s.z = (v2 >= 1.0f) ? 1.0f : 0.0f;
        s.w = (v3 >= 1.0f) ? 1.0f : 0.0f;
        *(float4*)&out[((t * B_DIM + b) * C_DIM + c) * N_DIM + n] = s;
        v0 = (v0 >= 1.0f) ? 0.0f : v0;
        v1 = (v1 >= 1.0f) ? 0.0f : v1;
        v2 = (v2 >= 1.0f) ? 0.0f : v2;
        v3 = (v3 >= 1.0f) ? 0.0f : v3;
    }
}

// ---------------------------------------------------------------------------
// kernel_launch. Inputs: 0:x 1:w1 2:g1 3:b1 4:w2 5:g2 6:b2
// Launch order chosen so ncu (-s 5 -c 1) profiles spmm2.
// ---------------------------------------------------------------------------
extern "C" void kernel_launch(void* const* d_in, const int* in_sizes, int n_in,
                              void* d_out, int out_size) {
    const float* x  = (const float*)d_in[0];
    const float* w1 = (const float*)d_in[1];
    const float* g1 = (const float*)d_in[2];
    const float* b1 = (const float*)d_in[3];
    const float* w2 = (const float*)d_in[4];
    const float* g2 = (const float*)d_in[5];
    const float* b2 = (const float*)d_in[6];
    float* out = (float*)d_out;

    float *p_xT, *p_h, *p_o, *p_m1, *p_r1, *p_m2, *p_r2;
    cudaGetSymbolAddress((void**)&p_xT, g_xT);
    cudaGetSymbolAddress((void**)&p_h,  g_h);
    cudaGetSymbolAddress((void**)&p_o,  g_o);
    cudaGetSymbolAddress((void**)&p_m1, g_mean1);
    cudaGetSymbolAddress((void**)&p_r1, g_rstd1);
    cudaGetSymbolAddress((void**)&p_m2, g_mean2);
    cudaGetSymbolAddress((void**)&p_r2, g_rstd2);

    transpose_x<<<(T_DIM * CJ / 4) / 256, 256>>>(x);                       // 1
    transpose_w2<<<dim3(H_DIM / 32, C_DIM / 32), dim3(32, 8)>>>(w2);       // 2
    sgemm1<<<dim3(H_DIM / 128, J_DIM / 128, T_DIM), 256>>>(w1, p_xT, p_h); // 3
    bn_stats<<<H_DIM, 256>>>(p_h, HJ, p_m1, p_r1);                         // 4
    lif1_mask<<<(H_DIM * JW) / 8, 256>>>(g1, b1);                          // 5
    spmm2<<<dim3(J_DIM / 32, T_DIM), 1024>>>();                            // 6 <- profiled
    bn_stats<<<C_DIM, 256>>>(p_o, CJ, p_m2, p_r2);                         // 7
    bn_lif2<<<(CJ / 4) / 256, 256>>>(g2, b2, out);                         // 8
}

// round 6
// speedup vs baseline: 1.3782x; 1.0656x over previous
#include <cuda_runtime.h>

// Problem dims
#define T_DIM 4
#define B_DIM 32
#define C_DIM 512
#define N_DIM 196
#define H_DIM 2048
#define J_DIM (B_DIM * N_DIM)          // 6272 = 49 * 128
#define JW    (J_DIM / 32)             // 196 mask words per (t,h)
#define HJ (H_DIM * J_DIM)             // 12,845,056
#define CJ (C_DIM * J_DIM)             //  3,211,264

// Scratch (static device memory)
__device__ float    g_xT[T_DIM * CJ];       // x transposed: (t, c, j)
__device__ float    g_h[T_DIM * HJ];        // hidden pre-act
__device__ float    g_o[T_DIM * CJ];        // output pre-act
__device__ float    g_w2T[H_DIM * C_DIM];   // w2 transposed to [H, C]
__device__ unsigned g_mask[T_DIM * JW * H_DIM]; // spike bits, layout [t][jw][h]
__device__ float    g_mean1[H_DIM];
__device__ float    g_rstd1[H_DIM];
__device__ float    g_mean2[C_DIM];
__device__ float    g_rstd2[C_DIM];

// ---- packed fp32x2 helpers (Blackwell FFMA2; lane-wise rn == fmaf) --------
__device__ __forceinline__ unsigned long long bcast2(float s) {
    unsigned long long d;
    asm("mov.b64 %0, {%1, %1};" : "=l"(d) : "f"(s));
    return d;
}
__device__ __forceinline__ void fma2(unsigned long long& acc,
                                     unsigned long long a,
                                     unsigned long long b) {
    asm("fma.rn.f32x2 %0, %1, %2, %0;" : "+l"(acc) : "l"(a), "l"(b));
}
__device__ __forceinline__ void unpack2(unsigned long long v, float& lo, float& hi) {
    asm("mov.b64 {%0, %1}, %2;" : "=f"(lo), "=f"(hi) : "l"(v));
}

// ---------------------------------------------------------------------------
// K0: transpose x (t,b,c,n) -> g_xT (t,c,j=b*n), float4 both sides.
// ---------------------------------------------------------------------------
__global__ void transpose_x(const float* __restrict__ x) {
    int idx = blockIdx.x * blockDim.x + threadIdx.x;   // over T*CJ/4
    int base = idx << 2;
    int t   = base / CJ;
    int rem = base - t * CJ;
    int c   = rem / J_DIM;
    int j   = rem - c * J_DIM;
    int b   = j / N_DIM;
    int n   = j - b * N_DIM;                            // n%4==0, n+3<196
    float4 v = *(const float4*)&x[((t * B_DIM + b) * C_DIM + c) * N_DIM + n];
    *(float4*)&g_xT[base] = v;
}

// ---------------------------------------------------------------------------
// K0b: transpose w2 [C,H] -> g_w2T [H,C]
// ---------------------------------------------------------------------------
__global__ void transpose_w2(const float* __restrict__ w2) {
    __shared__ float tile[32][33];
    int h0 = blockIdx.x * 32, c0 = blockIdx.y * 32;
    for (int r = threadIdx.y; r < 32; r += 8)
        tile[r][threadIdx.x] = w2[(c0 + r) * H_DIM + h0 + threadIdx.x];
    __syncthreads();
    for (int r = threadIdx.y; r < 32; r += 8)
        g_w2T[(h0 + r) * C_DIM + c0 + threadIdx.x] = tile[threadIdx.x][r];
}

// ---------------------------------------------------------------------------
// K1: SGEMM h = w1 @ xT per t, FFMA2 (f32x2) mainloop.
// 128x128 tile, BK=8, 256 threads, 8x8/thread (4+64 split), double-buffered.
// M-pairs come free from contiguous As fragments; B values are broadcast-
// packed. Per-element arithmetic is bitwise identical to the scalar version.
// ---------------------------------------------------------------------------
__global__ __launch_bounds__(256, 2) void sgemm1(
    const float* __restrict__ A, const float* __restrict__ B,
    float* __restrict__ C) {
    __shared__ float As[2][8][128];
    __shared__ float Bs[2][8][128];

    const float* Bt = B + blockIdx.z * CJ;
    float*       Ct = C + blockIdx.z * HJ;

    int tid = threadIdx.x;
    int m0 = blockIdx.x * 128;
    int n0 = blockIdx.y * 128;

    int arow = tid >> 1;
    int acol = (tid & 1) << 2;
    int brow = tid >> 5;
    int bcol = (tid & 31) << 2;

    const float* Ap = A  + (m0 + arow) * 512 + acol;
    const float* Bp = Bt + brow * J_DIM + n0 + bcol;

    int tx = tid & 15;
    int ty = tid >> 4;

    // acc[p][j]: p = m-pair index (rows ty*4 + {0,1},{2,3},{64,65},{66,67}),
    // j = column index (n0 + tx*4 + {0..3}, +64 + {0..3}).
    unsigned long long acc[4][8];
#pragma unroll
    for (int p = 0; p < 4; p++)
#pragma unroll
        for (int j = 0; j < 8; j++) acc[p][j] = 0ull;

    float4 a4 = *(const float4*)Ap;
    float4 b4 = *(const float4*)Bp;
    As[0][acol + 0][arow] = a4.x;
    As[0][acol + 1][arow] = a4.y;
    As[0][acol + 2][arow] = a4.z;
    As[0][acol + 3][arow] = a4.w;
    *(float4*)&Bs[0][brow][bcol] = b4;
    __syncthreads();

    int buf = 0;
    for (int k0 = 8; k0 <= 512; k0 += 8) {
        bool more = (k0 < 512);
        if (more) {
            Ap += 8;
            Bp += 8 * J_DIM;
            a4 = *(const float4*)Ap;
            b4 = *(const float4*)Bp;
        }
#pragma unroll
        for (int k = 0; k < 8; k++) {
            ulonglong2 A0 = *(const ulonglong2*)&As[buf][k][ty << 2];
            ulonglong2 A1 = *(const ulonglong2*)&As[buf][k][(ty << 2) + 64];
            float4 rb0 = *(const float4*)&Bs[buf][k][tx << 2];
            float4 rb1 = *(const float4*)&Bs[buf][k][(tx << 2) + 64];
            unsigned long long ap[4] = {A0.x, A0.y, A1.x, A1.y};
            float rb[8] = {rb0.x, rb0.y, rb0.z, rb0.w, rb1.x, rb1.y, rb1.z, rb1.w};
#pragma unroll
            for (int j = 0; j < 8; j++) {
                unsigned long long bb = bcast2(rb[j]);
#pragma unroll
                for (int p = 0; p < 4; p++)
                    fma2(acc[p][j], ap[p], bb);
            }
        }
        if (more) {
            buf ^= 1;
            As[buf][acol + 0][arow] = a4.x;
            As[buf][acol + 1][arow] = a4.y;
            As[buf][acol + 2][arow] = a4.z;
            As[buf][acol + 3][arow] = a4.w;
            *(float4*)&Bs[buf][brow][bcol] = b4;
            __syncthreads();
        }
    }

    // Epilogue: each pair p covers rows mLo, mLo+1.
#pragma unroll
    for (int p = 0; p < 4; p++) {
        int mLo = m0 + (ty << 2) + ((p < 2) ? (p << 1) : (64 + ((p - 2) << 1)));
        float lo[8], hi[8];
#pragma unroll
        for (int j = 0; j < 8; j++) unpack2(acc[p][j], lo[j], hi[j]);
        float* r0 = Ct + mLo * J_DIM + n0 + (tx << 2);
        float* r1 = r0 + J_DIM;
        *(float4*)r0        = make_float4(lo[0], lo[1], lo[2], lo[3]);
        *(float4*)(r0 + 64) = make_float4(lo[4], lo[5], lo[6], lo[7]);
        *(float4*)r1        = make_float4(hi[0], hi[1], hi[2], hi[3]);
        *(float4*)(r1 + 64) = make_float4(hi[4], hi[5], hi[6], hi[7]);
    }
}

// ---------------------------------------------------------------------------
// BN stats: one CTA per channel, fp64 accumulate, float4 loads.
// ---------------------------------------------------------------------------
__global__ __launch_bounds__(256) void bn_stats(
    const float* __restrict__ X, int tStride,
    float* __restrict__ meanOut, float* __restrict__ rstdOut) {
    int ch = blockIdx.x;
    const float* base = X + ch * J_DIM;
    double s1 = 0.0, s2 = 0.0;
    for (int t = 0; t < T_DIM; t++) {
        const float* p = base + t * tStride;
        for (int j = threadIdx.x * 4; j < J_DIM; j += 256 * 4) {
            float4 v = *(const float4*)&p[j];
            double a = v.x, b = v.y, c = v.z, d = v.w;
            s1 += a + b + c + d;
            s2 += a * a + b * b + c * c + d * d;
        }
    }
    __shared__ double sh1[256];
    __shared__ double sh2[256];
    sh1[threadIdx.x] = s1;
    sh2[threadIdx.x] = s2;
    __syncthreads();
    for (int s = 128; s > 0; s >>= 1) {
        if (threadIdx.x < s) {
            sh1[threadIdx.x] += sh1[threadIdx.x + s];
            sh2[threadIdx.x] += sh2[threadIdx.x + s];
        }
        __syncthreads();
    }
    if (threadIdx.x == 0) {
        double n    = (double)T_DIM * (double)J_DIM;
        double mean = sh1[0] / n;
        double var  = sh2[0] / n - mean * mean;
        meanOut[ch] = (float)mean;
        rstdOut[ch] = __frsqrt_rn(__fadd_rn((float)var, 1e-5f));
    }
}

// ---------------------------------------------------------------------------
// BN1 + LIF1 -> spike bitmask only.
// ---------------------------------------------------------------------------
__global__ __launch_bounds__(256) void lif1_mask(
    const float* __restrict__ gamma, const float* __restrict__ beta) {
    int gw   = (blockIdx.x << 3) + (threadIdx.x >> 5);  // global warp id
    int lane = threadIdx.x & 31;
    int h  = gw & (H_DIM - 1);
    int jw = gw >> 11;                                   // 0..195
    float m = g_mean1[h], r = g_rstd1[h];
    float g = gamma[h],   bt = beta[h];
    const float* p = g_h + h * J_DIM + (jw << 5) + lane;
    float v = 0.0f;
#pragma unroll
    for (int t = 0; t < T_DIM; t++) {
        float x = p[t * HJ];
        x = __fadd_rn(__fmul_rn(__fmul_rn(__fsub_rn(x, m), r), g), bt);
        v = __fadd_rn(v, __fmul_rn(__fsub_rn(x, v), 0.5f));
        unsigned mw = __ballot_sync(0xffffffffu, v >= 1.0f);
        if (lane == 0) g_mask[(t * JW + jw) * H_DIM + h] = mw;
        v = (v >= 1.0f) ? 0.0f : v;
    }
}

// ---------------------------------------------------------------------------
// K4: sparse spike GEMM. CTA = 32 j-columns x one t; warp w owns column j0+w.
// ---------------------------------------------------------------------------
__global__ __launch_bounds__(1024) void spmm2() {
    __shared__ unsigned words[H_DIM];        // 8 KB
    __shared__ float buf[128 * 33];          // 16.9 KB

    int tid  = threadIdx.x;
    int w    = tid >> 5;                     // warp id = local column
    int lane = tid & 31;
    int j0   = blockIdx.x * 32;
    int t    = blockIdx.y;

    // Phase 1: contiguous mask load for this (t, jw) block.
    {
        const unsigned* mp = g_mask + (t * JW + blockIdx.x) * H_DIM;
        words[tid]        = mp[tid];
        words[tid + 1024] = mp[tid + 1024];
    }
    __syncthreads();

    // Phase 2: accumulate active rows of w2T for column j0+w.
    float4 acc0 = make_float4(0.f, 0.f, 0.f, 0.f);
    float4 acc1 = acc0, acc2 = acc0, acc3 = acc0;
    int c0 = lane << 2;
    for (int wi = 0; wi < H_DIM / 32; wi++) {
        unsigned bit = (words[(wi << 5) + lane] >> w) & 1u;
        unsigned m = __ballot_sync(0xffffffffu, bit);
        while (m) {
            int b = __ffs(m) - 1;
            m &= m - 1;
            int h = (wi << 5) + b;
            const float* rp = g_w2T + h * C_DIM + c0;
            float4 v0 = *(const float4*)(rp);
            float4 v1 = *(const float4*)(rp + 128);
            float4 v2 = *(const float4*)(rp + 256);
            float4 v3 = *(const float4*)(rp + 384);
            acc0.x += v0.x; acc0.y += v0.y; acc0.z += v0.z; acc0.w += v0.w;
            acc1.x += v1.x; acc1.y += v1.y; acc1.z += v1.z; acc1.w += v1.w;
            acc2.x += v2.x; acc2.y += v2.y; acc2.z += v2.z; acc2.w += v2.w;
            acc3.x += v3.x; acc3.y += v3.y; acc3.z += v3.z; acc3.w += v3.w;
        }
    }

    // Epilogue: 4 chunks of 128 c-rows, staged for coalesced writes.
#pragma unroll
    for (int q = 0; q < 4; q++) {
        float4 a = (q == 0) ? acc0 : (q == 1) ? acc1 : (q == 2) ? acc2 : acc3;
        __syncthreads();
        buf[(c0 + 0) * 33 + w] = a.x;
        buf[(c0 + 1) * 33 + w] = a.y;
        buf[(c0 + 2) * 33 + w] = a.z;
        buf[(c0 + 3) * 33 + w] = a.w;
        __syncthreads();
        int c_local = tid >> 3;              // 0..127
        int jj = (tid & 7) << 2;             // 0..28
        float4 o;
        o.x = buf[c_local * 33 + jj + 0];
        o.y = buf[c_local * 33 + jj + 1];
        o.z = buf[c_local * 33 + jj + 2];
        o.w = buf[c_local * 33 + jj + 3];
        *(float4*)&g_o[t * CJ + (q * 128 + c_local) * J_DIM + j0 + jj] = o;
    }
}

// ---------------------------------------------------------------------------
// BN2 + LIF2 + transpose to (T,B,C,N), float4.
// ---------------------------------------------------------------------------
__global__ __launch_bounds__(256) void bn_lif2(
    const float* __restrict__ gamma, const float* __restrict__ beta,
    float* __restrict__ out) {
    int idx = blockIdx.x * blockDim.x + threadIdx.x;   // over CJ/4
    int base = idx << 2;
    int c = base / J_DIM;
    int j = base - c * J_DIM;
    int b = j / N_DIM;
    int n = j - b * N_DIM;
    float m = g_mean2[c], r = g_rstd2[c];
    float g = gamma[c],   bt = beta[c];
    float v0 = 0.f, v1 = 0.f, v2 = 0.f, v3 = 0.f;
#pragma unroll
    for (int t = 0; t < T_DIM; t++) {
        float4 x = *(const float4*)&g_o[base + t * CJ];
        float a0 = __fadd_rn(__fmul_rn(__fmul_rn(__fsub_rn(x.x, m), r), g), bt);
        float a1 = __fadd_rn(__fmul_rn(__fmul_rn(__fsub_rn(x.y, m), r), g), bt);
        float a2 = __fadd_rn(__fmul_rn(__fmul_rn(__fsub_rn(x.z, m), r), g), bt);
        float a3 = __fadd_rn(__fmul_rn(__fmul_rn(__fsub_rn(x.w, m), r), g), bt);
        v0 = __fadd_rn(v0, __fmul_rn(__fsub_rn(a0, v0), 0.5f));
        v1 = __fadd_rn(v1, __fmul_rn(__fsub_rn(a1, v1), 0.5f));
        v2 = __fadd_rn(v2, __fmul_rn(__fsub_rn(a2, v2), 0.5f));
        v3 = __fadd_rn(v3, __fmul_rn(__fsub_rn(a3, v3), 0.5f));
        float4 s;
        s.x = (v0 >= 1.0f) ? 1.0f : 0.0f;
        s.y = (v1 >= 1.0f) ? 1.0f : 0.0f;
        s.z = (v2 >= 1.0f) ? 1.0f : 0.0f;
        s.w = (v3 >= 1.0f) ? 1.0f : 0.0f;
        *(float4*)&out[((t * B_DIM + b) * C_DIM + c) * N_DIM + n] = s;
        v0 = (v0 >= 1.0f) ? 0.0f : v0;
        v1 = (v1 >= 1.0f) ? 0.0f : v1;
        v2 = (v2 >= 1.0f) ? 0.0f : v2;
        v3 = (v3 >= 1.0f) ? 0.0f : v3;
    }
}

// ---------------------------------------------------------------------------
// kernel_launch. Inputs: 0:x 1:w1 2:g1 3:b1 4:w2 5:g2 6:b2
// ---------------------------------------------------------------------------
extern "C" void kernel_launch(void* const* d_in, const int* in_sizes, int n_in,
                              void* d_out, int out_size) {
    const float* x  = (const float*)d_in[0];
    const float* w1 = (const float*)d_in[1];
    const float* g1 = (const float*)d_in[2];
    const float* b1 = (const float*)d_in[3];
    const float* w2 = (const float*)d_in[4];
    const float* g2 = (const float*)d_in[5];
    const float* b2 = (const float*)d_in[6];
    float* out = (float*)d_out;

    float *p_xT, *p_h, *p_o, *p_m1, *p_r1, *p_m2, *p_r2;
    cudaGetSymbolAddress((void**)&p_xT, g_xT);
    cudaGetSymbolAddress((void**)&p_h,  g_h);
    cudaGetSymbolAddress((void**)&p_o,  g_o);
    cudaGetSymbolAddress((void**)&p_m1, g_mean1);
    cudaGetSymbolAddress((void**)&p_r1, g_rstd1);
    cudaGetSymbolAddress((void**)&p_m2, g_mean2);
    cudaGetSymbolAddress((void**)&p_r2, g_rstd2);

    transpose_x<<<(T_DIM * CJ / 4) / 256, 256>>>(x);                       // 1
    transpose_w2<<<dim3(H_DIM / 32, C_DIM / 32), dim3(32, 8)>>>(w2);       // 2
    sgemm1<<<dim3(H_DIM / 128, J_DIM / 128, T_DIM), 256>>>(w1, p_xT, p_h); // 3
    bn_stats<<<H_DIM, 256>>>(p_h, HJ, p_m1, p_r1);                         // 4
    lif1_mask<<<(H_DIM * JW) / 8, 256>>>(g1, b1);                          // 5
    spmm2<<<dim3(J_DIM / 32, T_DIM), 1024>>>();                            // 6
    bn_stats<<<C_DIM, 256>>>(p_o, CJ, p_m2, p_r2);                         // 7
    bn_lif2<<<(CJ / 4) / 256, 256>>>(g2, b2, out);                         // 8
}